// round 2
// baseline (speedup 1.0000x reference)
#include <cuda_runtime.h>
#include <cuda_bf16.h>

#define NN 16384
#define DD 64
#define BLK 128
#define KC 32

// ---------------- device scratch (no allocations allowed) ----------------
__device__ double g_Q;
__device__ double g_Sa, g_Sxi, g_Sy;
__device__ float  g_w[NN];

// ---------------- helpers ----------------
// Scalars like coeff/degree/C/lambd come from python ints; defensively accept
// either int32 or float32 bit patterns.
__device__ __forceinline__ float scal_as_float(const int* p) {
    int v = *p;
    if (v < 0 || v >= 0x00800000) return __int_as_float(v);
    return (float)v;
}
__device__ __forceinline__ int scal_as_int(const int* p) {
    int v = *p;
    if (v < 0 || v >= 0x00800000) return (int)(__int_as_float(v) + 0.5f);
    return v;
}

// ---------------- kernels ----------------
__global__ void svm_zero_kernel() {
    g_Q = 0.0; g_Sa = 0.0; g_Sxi = 0.0; g_Sy = 0.0;
}

__global__ void svm_prep_kernel(const float* __restrict__ alpha,
                                const float* __restrict__ xi,
                                const float* __restrict__ y) {
    int i = blockIdx.x * blockDim.x + threadIdx.x;
    float a = 0.f, xr = 0.f, yv = 0.f;
    if (i < NN) {
        a  = fmaxf(alpha[i], 0.f);
        xr = fmaxf(xi[i], 0.f);
        yv = y[i];
        g_w[i] = a * yv;
    }
    // warp reduce
    #pragma unroll
    for (int o = 16; o > 0; o >>= 1) {
        a  += __shfl_down_sync(0xffffffffu, a,  o);
        xr += __shfl_down_sync(0xffffffffu, xr, o);
        yv += __shfl_down_sync(0xffffffffu, yv, o);
    }
    if ((threadIdx.x & 31) == 0) {
        atomicAdd(&g_Sa,  (double)a);
        atomicAdd(&g_Sxi, (double)xr);
        atomicAdd(&g_Sy,  (double)yv);
    }
}

// Quadratic form: Q = sum_{i,j} y_i * w_j * (x_i . x_j + coeff)^degree
// 128x128 tile per block, 256 threads, 8x8 per-thread micro-tile.
__global__ __launch_bounds__(256)
void svm_quad_kernel(const float* __restrict__ x,
                     const float* __restrict__ y,
                     const int*   __restrict__ coeff_p,
                     const int*   __restrict__ degree_p) {
    // transposed smem layout [k][row], row-stride padded to 132 (mult of 4 for
    // float4 alignment, +4 to break the 32-bank stride)
    __shared__ float As[KC][BLK + 4];
    __shared__ float Bs[KC][BLK + 4];
    __shared__ double red[8];

    const int tid  = threadIdx.x;
    const int tx   = tid & 15;       // 0..15 -> 8 cols each
    const int ty   = tid >> 4;       // 0..15 -> 8 rows each
    const int bi   = blockIdx.y * BLK;
    const int bj   = blockIdx.x * BLK;

    const int lrow = tid >> 1;       // 0..127 : smem row this thread fills
    const int half = tid & 1;        // which 16-wide half of the K-chunk

    const float* __restrict__ xa = x + (size_t)(bi + lrow) * DD;
    const float* __restrict__ xb = x + (size_t)(bj + lrow) * DD;

    float acc[8][8];
    #pragma unroll
    for (int m = 0; m < 8; ++m)
        #pragma unroll
        for (int n = 0; n < 8; ++n) acc[m][n] = 0.f;

    #pragma unroll
    for (int kc = 0; kc < DD; kc += KC) {
        // each thread loads 16 floats (4x float4) of one row into each tile
        #pragma unroll
        for (int v = 0; v < 4; ++v) {
            const int k0 = half * 16 + v * 4;
            float4 fa = *(const float4*)(xa + kc + k0);
            float4 fb = *(const float4*)(xb + kc + k0);
            As[k0 + 0][lrow] = fa.x; As[k0 + 1][lrow] = fa.y;
            As[k0 + 2][lrow] = fa.z; As[k0 + 3][lrow] = fa.w;
            Bs[k0 + 0][lrow] = fb.x; Bs[k0 + 1][lrow] = fb.y;
            Bs[k0 + 2][lrow] = fb.z; Bs[k0 + 3][lrow] = fb.w;
        }
        __syncthreads();

        #pragma unroll 4
        for (int k = 0; k < KC; ++k) {
            float af[8], bf[8];
            *(float4*)&af[0] = *(const float4*)&As[k][ty * 8];
            *(float4*)&af[4] = *(const float4*)&As[k][ty * 8 + 4];
            *(float4*)&bf[0] = *(const float4*)&Bs[k][tx * 8];
            *(float4*)&bf[4] = *(const float4*)&Bs[k][tx * 8 + 4];
            #pragma unroll
            for (int m = 0; m < 8; ++m)
                #pragma unroll
                for (int n = 0; n < 8; ++n)
                    acc[m][n] = fmaf(af[m], bf[n], acc[m][n]);
        }
        __syncthreads();
    }

    // ---- epilogue: (dot + coeff)^degree * y_i * w_j, reduce to scalar ----
    const float coeff = scal_as_float(coeff_p);
    const int   deg   = scal_as_int(degree_p);

    float yv[8], wv[8];
    #pragma unroll
    for (int m = 0; m < 8; ++m) yv[m] = y[bi + ty * 8 + m];
    #pragma unroll
    for (int n = 0; n < 8; ++n) wv[n] = g_w[bj + tx * 8 + n];

    float partial = 0.f;
    #pragma unroll
    for (int m = 0; m < 8; ++m) {
        float rowsum = 0.f;
        #pragma unroll
        for (int n = 0; n < 8; ++n) {
            float base = acc[m][n] + coeff;
            float p = 1.f;
            for (int d = 0; d < deg; ++d) p *= base;
            rowsum = fmaf(wv[n], p, rowsum);
        }
        partial = fmaf(yv[m], rowsum, partial);
    }

    // block reduce -> double atomic
    #pragma unroll
    for (int o = 16; o > 0; o >>= 1)
        partial += __shfl_down_sync(0xffffffffu, partial, o);
    if ((tid & 31) == 0) red[tid >> 5] = (double)partial;
    __syncthreads();
    if (tid == 0) {
        double s = 0.0;
        #pragma unroll
        for (int w = 0; w < 8; ++w) s += red[w];
        atomicAdd(&g_Q, s);
    }
}

__global__ void svm_fin_kernel(const float* __restrict__ b,
                               const int*   __restrict__ C_p,
                               const int*   __restrict__ lambd_p,
                               float* __restrict__ out) {
    double C  = (double)scal_as_float(C_p);
    double la = (double)scal_as_float(lambd_p);
    double Q = g_Q, Sa = g_Sa, Sxi = g_Sxi, Sy = g_Sy;
    double loss = 0.5 * Sa + C * Sxi
                + la * ((Q + (double)b[0] * Sy + Sxi) / (double)NN - 1.0);
    out[0] = (float)loss;
}

// ---------------- launch ----------------
extern "C" void kernel_launch(void* const* d_in, const int* in_sizes, int n_in,
                              void* d_out, int out_size) {
    const float* x      = (const float*)d_in[0];
    const float* y      = (const float*)d_in[1];
    const float* alpha  = (const float*)d_in[2];
    const float* xi     = (const float*)d_in[3];
    const float* b      = (const float*)d_in[4];
    const int*   coeff  = (const int*)d_in[5];
    const int*   degree = (const int*)d_in[6];
    const int*   Cc     = (const int*)d_in[7];
    const int*   lambd  = (const int*)d_in[8];
    float* out = (float*)d_out;

    svm_zero_kernel<<<1, 1>>>();
    svm_prep_kernel<<<(NN + 255) / 256, 256>>>(alpha, xi, y);
    dim3 grid(NN / BLK, NN / BLK);
    svm_quad_kernel<<<grid, 256>>>(x, y, coeff, degree);
    svm_fin_kernel<<<1, 1>>>(b, Cc, lambd, out);
}

// round 4
// speedup vs baseline: 1.7596x; 1.7596x over previous
#include <cuda_runtime.h>
#include <cuda_bf16.h>
#include <cstdint>

#define NN 16384
#define DD 64
#define BLK 128           // CTA tile is BLK x BLK
#define NTILES (NN / BLK) // 128

// ---------------- device scratch (no allocations allowed) ----------------
__device__ double g_Q;
__device__ double g_Sa, g_Sxi, g_Sy;
__device__ float  g_w[NN];
__device__ __align__(128) __nv_bfloat16 g_hi[NN * DD];
__device__ __align__(128) __nv_bfloat16 g_lo[NN * DD];

// ---------------- helpers ----------------
__device__ __forceinline__ uint32_t smem_u32(const void* p) {
    uint32_t a;
    asm("{ .reg .u64 t; cvta.to.shared.u64 t, %1; cvt.u32.u64 %0, t; }"
        : "=r"(a) : "l"(p));
    return a;
}

__device__ __forceinline__ void ldsm_x4(uint32_t& r0, uint32_t& r1,
                                        uint32_t& r2, uint32_t& r3, uint32_t addr) {
    asm volatile("ldmatrix.sync.aligned.m8n8.x4.shared.b16 {%0,%1,%2,%3}, [%4];"
                 : "=r"(r0), "=r"(r1), "=r"(r2), "=r"(r3) : "r"(addr));
}

__device__ __forceinline__ void mma_16816(float* c, const uint32_t* a, const uint32_t* b) {
    asm volatile(
        "mma.sync.aligned.m16n8k16.row.col.f32.bf16.bf16.f32 "
        "{%0,%1,%2,%3}, {%4,%5,%6,%7}, {%8,%9}, {%0,%1,%2,%3};"
        : "+f"(c[0]), "+f"(c[1]), "+f"(c[2]), "+f"(c[3])
        : "r"(a[0]), "r"(a[1]), "r"(a[2]), "r"(a[3]), "r"(b[0]), "r"(b[1]));
}

// scalars may be int32 or float32 bit patterns
__device__ __forceinline__ float scal_as_float(const int* p) {
    int v = *p;
    if (v < 0 || v >= 0x00800000) return __int_as_float(v);
    return (float)v;
}
__device__ __forceinline__ int scal_as_int(const int* p) {
    int v = *p;
    if (v < 0 || v >= 0x00800000) return (int)(__int_as_float(v) + 0.5f);
    return v;
}

// ---------------- small kernels ----------------
__global__ void svm_zero_kernel() {
    g_Q = 0.0; g_Sa = 0.0; g_Sxi = 0.0; g_Sy = 0.0;
}

// relu sums + w + bf16 hi/lo split of x
__global__ void svm_prep_kernel(const float* __restrict__ x,
                                const float* __restrict__ alpha,
                                const float* __restrict__ xi,
                                const float* __restrict__ y) {
    int i = blockIdx.x * blockDim.x + threadIdx.x;
    for (int e = i; e < NN * DD; e += gridDim.x * blockDim.x) {
        float v = x[e];
        __nv_bfloat16 h = __float2bfloat16_rn(v);
        g_hi[e] = h;
        g_lo[e] = __float2bfloat16_rn(v - __bfloat162float(h));
    }
    float a = 0.f, xr = 0.f, yv = 0.f;
    if (i < NN) {
        a  = fmaxf(alpha[i], 0.f);
        xr = fmaxf(xi[i], 0.f);
        yv = y[i];
        g_w[i] = a * yv;
    }
    #pragma unroll
    for (int o = 16; o > 0; o >>= 1) {
        a  += __shfl_down_sync(0xffffffffu, a,  o);
        xr += __shfl_down_sync(0xffffffffu, xr, o);
        yv += __shfl_down_sync(0xffffffffu, yv, o);
    }
    if ((threadIdx.x & 31) == 0 && i < NN) {
        atomicAdd(&g_Sa,  (double)a);
        atomicAdd(&g_Sxi, (double)xr);
        atomicAdd(&g_Sy,  (double)yv);
    }
}

// ---------------- main Gram-tile kernel (mma.sync bf16) ----------------
// smem tiles: 128 rows x 64 bf16 (128B/row) with SW128 chunk swizzle:
//   byte off = row*128 + ((c16 ^ (row&7)) * 16),  c16 = 0..7
#define T_AHI 0
#define T_ALO 16384
#define T_BHI 32768
#define T_BLO 49152
#define OFF_W 65536
#define OFF_Y 66048
#define SMEM_BYTES (66560 + 256)

__global__ __launch_bounds__(256)
void svm_quad_mma_kernel(const float* __restrict__ y,
                         const int* __restrict__ coeff_p,
                         const int* __restrict__ degree_p) {
    extern __shared__ char smem_raw[];
    const uint32_t raw = smem_u32(smem_raw);
    const uint32_t base = (raw + 127u) & ~127u;
    char* smem = smem_raw + (base - raw);

    const int tid = threadIdx.x;
    const int wid = tid >> 5;
    const int lid = tid & 31;
    const int wm  = wid & 3;   // 4 warps along M
    const int wn  = wid >> 2;  // 2 warps along N
    const int bi = blockIdx.y * BLK;
    const int bj = blockIdx.x * BLK;

    // ---- load tiles: 4 x (1024 chunks of 16B), swizzled ----
    {
        const uint4* sAhi = (const uint4*)(g_hi + (size_t)bi * DD);
        const uint4* sAlo = (const uint4*)(g_lo + (size_t)bi * DD);
        const uint4* sBhi = (const uint4*)(g_hi + (size_t)bj * DD);
        const uint4* sBlo = (const uint4*)(g_lo + (size_t)bj * DD);
        #pragma unroll
        for (int it = 0; it < 4; ++it) {
            int i = tid + it * 256;        // 0..1023 = row*8 + c16
            int row = i >> 3, c16 = i & 7;
            int sw = row * 128 + ((c16 ^ (row & 7)) << 4);
            *(uint4*)(smem + T_AHI + sw) = sAhi[i];
            *(uint4*)(smem + T_ALO + sw) = sAlo[i];
            *(uint4*)(smem + T_BHI + sw) = sBhi[i];
            *(uint4*)(smem + T_BLO + sw) = sBlo[i];
        }
        if (tid < 128) {
            *(float*)(smem + OFF_W + tid * 4) = g_w[bj + tid];
            *(float*)(smem + OFF_Y + tid * 4) = y[bi + tid];
        }
    }
    __syncthreads();

    // ---- per-lane ldmatrix address components ----
    const int q   = lid >> 3;   // matrix index 0..3
    const int seg = lid & 7;    // row within matrix
    // A frag (16x16 of row-major A): matrices [m0-7,k0-7],[m8-15,k0-7],[m0-7,k8-15],[m8-15,k8-15]
    const int rowA0 = wm * 32 + seg + ((q & 1) << 3);       // am=0 frag
    const int chA   = q >> 1;                                // + 2*ks
    // B frag (col-major KxN, n-major rows in smem): matrices [n0-7,k0-7],[n0-7,k8-15],[n8-15,k0-7],[n8-15,k8-15]
    const int rowB0 = wn * 64 + seg + ((q >> 1) << 3);      // bn2=0 pair
    const int chB   = q & 1;                                 // + 2*ks

    float acc[2][8][4];
    #pragma unroll
    for (int am = 0; am < 2; ++am)
        #pragma unroll
        for (int bn = 0; bn < 8; ++bn)
            #pragma unroll
            for (int r = 0; r < 4; ++r) acc[am][bn][r] = 0.f;

    const uint32_t aBases[3] = { base + T_AHI, base + T_AHI, base + T_ALO };
    const uint32_t bBases[3] = { base + T_BHI, base + T_BLO, base + T_BHI };

    #pragma unroll
    for (int pass = 0; pass < 3; ++pass) {
        const uint32_t aB = aBases[pass];
        const uint32_t bB = bBases[pass];
        #pragma unroll
        for (int ks = 0; ks < 4; ++ks) {
            // A fragments: am = 0,1  (m16 each)
            uint32_t af[2][4];
            #pragma unroll
            for (int am = 0; am < 2; ++am) {
                int row = rowA0 + am * 16;
                int ch  = (chA + 2 * ks) ^ (row & 7);
                ldsm_x4(af[am][0], af[am][1], af[am][2], af[am][3],
                        aB + row * 128 + (ch << 4));
            }
            // B fragments: bn2 = 0..3, each ldsm.x4 covers n16 (2 n-frags)
            uint32_t bf[8][2];
            #pragma unroll
            for (int bn2 = 0; bn2 < 4; ++bn2) {
                int row = rowB0 + bn2 * 16;
                int ch  = (chB + 2 * ks) ^ (row & 7);
                ldsm_x4(bf[bn2 * 2][0], bf[bn2 * 2][1],
                        bf[bn2 * 2 + 1][0], bf[bn2 * 2 + 1][1],
                        bB + row * 128 + (ch << 4));
            }
            // MMAs
            #pragma unroll
            for (int am = 0; am < 2; ++am)
                #pragma unroll
                for (int bn = 0; bn < 8; ++bn)
                    mma_16816(acc[am][bn], af[am], bf[bn]);
        }
    }

    // ---- epilogue: (v + coeff)^degree * y_i * w_j ----
    const float coeff = scal_as_float(coeff_p);
    const int   deg   = scal_as_int(degree_p);
    const float* sw_w = (const float*)(smem + OFF_W);
    const float* sw_y = (const float*)(smem + OFF_Y);

    const int rBase = wm * 32 + (lid >> 2);   // +0/+8 within frag, +16 for am=1
    const int cBase = wn * 64 + 2 * (lid & 3);

    float part = 0.f;
    #pragma unroll
    for (int am = 0; am < 2; ++am) {
        const float y0 = sw_y[rBase + am * 16];
        const float y1 = sw_y[rBase + am * 16 + 8];
        float s0 = 0.f, s1 = 0.f;
        #pragma unroll
        for (int bn = 0; bn < 8; ++bn) {
            const float w0 = sw_w[cBase + bn * 8];
            const float w1 = sw_w[cBase + bn * 8 + 1];
            if (deg == 3) {
                float v0 = acc[am][bn][0] + coeff;
                float v1 = acc[am][bn][1] + coeff;
                float v2 = acc[am][bn][2] + coeff;
                float v3 = acc[am][bn][3] + coeff;
                s0 = fmaf(w0, v0 * v0 * v0, s0);
                s0 = fmaf(w1, v1 * v1 * v1, s0);
                s1 = fmaf(w0, v2 * v2 * v2, s1);
                s1 = fmaf(w1, v3 * v3 * v3, s1);
            } else {
                #pragma unroll
                for (int r = 0; r < 4; ++r) {
                    float v = acc[am][bn][r] + coeff;
                    float p = 1.f;
                    for (int d = 0; d < deg; ++d) p *= v;
                    float wv = (r & 1) ? w1 : w0;
                    if (r < 2) s0 = fmaf(wv, p, s0);
                    else       s1 = fmaf(wv, p, s1);
                }
            }
        }
        part = fmaf(y0, s0, part);
        part = fmaf(y1, s1, part);
    }

    // ---- block reduce -> global double atomic ----
    #pragma unroll
    for (int o = 16; o > 0; o >>= 1)
        part += __shfl_down_sync(0xffffffffu, part, o);
    __shared__ float red[8];
    if (lid == 0) red[wid] = part;
    __syncthreads();
    if (tid == 0) {
        float s = 0.f;
        #pragma unroll
        for (int w = 0; w < 8; ++w) s += red[w];
        atomicAdd(&g_Q, (double)s);
    }
}

__global__ void svm_fin_kernel(const float* __restrict__ b,
                               const int*   __restrict__ C_p,
                               const int*   __restrict__ lambd_p,
                               float* __restrict__ out) {
    double C  = (double)scal_as_float(C_p);
    double la = (double)scal_as_float(lambd_p);
    double Q = g_Q, Sa = g_Sa, Sxi = g_Sxi, Sy = g_Sy;
    double loss = 0.5 * Sa + C * Sxi
                + la * ((Q + (double)b[0] * Sy + Sxi) / (double)NN - 1.0);
    out[0] = (float)loss;
}

// ---------------- launch ----------------
extern "C" void kernel_launch(void* const* d_in, const int* in_sizes, int n_in,
                              void* d_out, int out_size) {
    const float* x      = (const float*)d_in[0];
    const float* y      = (const float*)d_in[1];
    const float* alpha  = (const float*)d_in[2];
    const float* xi     = (const float*)d_in[3];
    const float* b      = (const float*)d_in[4];
    const int*   coeff  = (const int*)d_in[5];
    const int*   degree = (const int*)d_in[6];
    const int*   Cc     = (const int*)d_in[7];
    const int*   lambd  = (const int*)d_in[8];
    float* out = (float*)d_out;

    static bool attr_set = false;
    if (!attr_set) {
        cudaFuncSetAttribute(svm_quad_mma_kernel,
                             cudaFuncAttributeMaxDynamicSharedMemorySize, SMEM_BYTES);
        attr_set = true;
    }

    svm_zero_kernel<<<1, 1>>>();
    svm_prep_kernel<<<256, 256>>>(x, alpha, xi, y);
    dim3 grid(NTILES, NTILES);
    svm_quad_mma_kernel<<<grid, 256, SMEM_BYTES>>>(y, coeff, degree);
    svm_fin_kernel<<<1, 1>>>(b, Cc, lambd, out);
}

// round 5
// speedup vs baseline: 4.1057x; 2.3334x over previous
#include <cuda_runtime.h>
#include <cuda_bf16.h>
#include <cstdint>

#define NN 16384
#define DD 64
#define BLK 128           // CTA tile is BLK x BLK
#define NTILES (NN / BLK) // 128
#define NPAIRS (NTILES * (NTILES + 1) / 2)   // 8256 upper-tri tiles

// ---------------- device scratch (no allocations allowed) ----------------
__device__ double g_Q;
__device__ double g_Sa, g_Sxi, g_Sy;
__device__ float  g_w[NN];
__device__ __align__(128) __nv_bfloat16 g_hi[NN * DD];
__device__ __align__(128) __nv_bfloat16 g_lo[NN * DD];

// ---------------- helpers ----------------
__device__ __forceinline__ uint32_t smem_u32(const void* p) {
    uint32_t a;
    asm("{ .reg .u64 t; cvta.to.shared.u64 t, %1; cvt.u32.u64 %0, t; }"
        : "=r"(a) : "l"(p));
    return a;
}

__device__ __forceinline__ void ldsm_x4(uint32_t& r0, uint32_t& r1,
                                        uint32_t& r2, uint32_t& r3, uint32_t addr) {
    asm volatile("ldmatrix.sync.aligned.m8n8.x4.shared.b16 {%0,%1,%2,%3}, [%4];"
                 : "=r"(r0), "=r"(r1), "=r"(r2), "=r"(r3) : "r"(addr));
}

__device__ __forceinline__ void mma_16816(float* c, const uint32_t* a, const uint32_t* b) {
    asm volatile(
        "mma.sync.aligned.m16n8k16.row.col.f32.bf16.bf16.f32 "
        "{%0,%1,%2,%3}, {%4,%5,%6,%7}, {%8,%9}, {%0,%1,%2,%3};"
        : "+f"(c[0]), "+f"(c[1]), "+f"(c[2]), "+f"(c[3])
        : "r"(a[0]), "r"(a[1]), "r"(a[2]), "r"(a[3]), "r"(b[0]), "r"(b[1]));
}

// scalars may be int32 or float32 bit patterns
__device__ __forceinline__ float scal_as_float(const int* p) {
    int v = *p;
    if (v < 0 || v >= 0x00800000) return __int_as_float(v);
    return (float)v;
}
__device__ __forceinline__ int scal_as_int(const int* p) {
    int v = *p;
    if (v < 0 || v >= 0x00800000) return (int)(__int_as_float(v) + 0.5f);
    return v;
}

// ---------------- small kernels ----------------
__global__ void svm_zero_kernel() {
    g_Q = 0.0; g_Sa = 0.0; g_Sxi = 0.0; g_Sy = 0.0;
}

// relu sums + w + bf16 hi/lo split of x
__global__ void svm_prep_kernel(const float* __restrict__ x,
                                const float* __restrict__ alpha,
                                const float* __restrict__ xi,
                                const float* __restrict__ y) {
    int i = blockIdx.x * blockDim.x + threadIdx.x;
    for (int e = i; e < NN * DD; e += gridDim.x * blockDim.x) {
        float v = x[e];
        __nv_bfloat16 h = __float2bfloat16_rn(v);
        g_hi[e] = h;
        g_lo[e] = __float2bfloat16_rn(v - __bfloat162float(h));
    }
    float a = 0.f, xr = 0.f, yv = 0.f;
    if (i < NN) {
        a  = fmaxf(alpha[i], 0.f);
        xr = fmaxf(xi[i], 0.f);
        yv = y[i];
        g_w[i] = a * yv;
    }
    #pragma unroll
    for (int o = 16; o > 0; o >>= 1) {
        a  += __shfl_down_sync(0xffffffffu, a,  o);
        xr += __shfl_down_sync(0xffffffffu, xr, o);
        yv += __shfl_down_sync(0xffffffffu, yv, o);
    }
    if ((threadIdx.x & 31) == 0 && i < NN) {
        atomicAdd(&g_Sa,  (double)a);
        atomicAdd(&g_Sxi, (double)xr);
        atomicAdd(&g_Sy,  (double)yv);
    }
}

// ---------------- main Gram-tile kernel (upper-tri, mma.sync bf16) ----------------
// smem tiles: 128 rows x 64 bf16 (128B/row), SW128 chunk swizzle:
//   byte off = row*128 + ((c16 ^ (row&7)) * 16)
#define T_AHI 0
#define T_ALO 16384
#define T_BHI 32768
#define T_BLO 49152
#define OFF_WJ 65536
#define OFF_YI 66048
#define OFF_WI 66560
#define OFF_YJ 67072
#define SMEM_BYTES (67584 + 256)

__global__ __launch_bounds__(256)
void svm_quad_mma_kernel(const float* __restrict__ y,
                         const int* __restrict__ coeff_p,
                         const int* __restrict__ degree_p) {
    extern __shared__ char smem_raw[];
    const uint32_t raw = smem_u32(smem_raw);
    const uint32_t base = (raw + 127u) & ~127u;
    char* smem = smem_raw + (base - raw);

    const int tid = threadIdx.x;
    const int wid = tid >> 5;
    const int lid = tid & 31;
    const int wm  = wid & 3;   // 4 warps along M
    const int wn  = wid >> 2;  // 2 warps along N

    // ---- triangular decode: blockIdx.x -> (I, J), I <= J ----
    int idx = blockIdx.x;
    int I = (int)((2.0 * NTILES + 1.0
                   - sqrt((2.0 * NTILES + 1.0) * (2.0 * NTILES + 1.0) - 8.0 * idx)) * 0.5);
    if (I > NTILES - 1) I = NTILES - 1;
    if (I < 0) I = 0;
    // base(I) = I*NTILES - I*(I-1)/2
    #pragma unroll 1
    while (I > 0 && (I * NTILES - (I * (I - 1)) / 2) > idx) --I;
    #pragma unroll 1
    while (((I + 1) * NTILES - ((I + 1) * I) / 2) <= idx) ++I;
    const int J = I + (idx - (I * NTILES - (I * (I - 1)) / 2));
    const int bi = I * BLK;
    const int bj = J * BLK;
    const bool offdiag = (I != J);

    // ---- load tiles (4 x 1024 x 16B chunks, swizzled) + weight vectors ----
    {
        const uint4* sAhi = (const uint4*)(g_hi + (size_t)bi * DD);
        const uint4* sAlo = (const uint4*)(g_lo + (size_t)bi * DD);
        const uint4* sBhi = (const uint4*)(g_hi + (size_t)bj * DD);
        const uint4* sBlo = (const uint4*)(g_lo + (size_t)bj * DD);
        #pragma unroll
        for (int it = 0; it < 4; ++it) {
            int i = tid + it * 256;        // 0..1023 = row*8 + c16
            int row = i >> 3, c16 = i & 7;
            int sw = row * 128 + ((c16 ^ (row & 7)) << 4);
            *(uint4*)(smem + T_AHI + sw) = sAhi[i];
            *(uint4*)(smem + T_ALO + sw) = sAlo[i];
            *(uint4*)(smem + T_BHI + sw) = sBhi[i];
            *(uint4*)(smem + T_BLO + sw) = sBlo[i];
        }
        if (tid < 128) {
            *(float*)(smem + OFF_WJ + tid * 4) = g_w[bj + tid];
            *(float*)(smem + OFF_YI + tid * 4) = y[bi + tid];
            *(float*)(smem + OFF_WI + tid * 4) = g_w[bi + tid];
            *(float*)(smem + OFF_YJ + tid * 4) = y[bj + tid];
        }
    }
    __syncthreads();

    // ---- per-lane ldmatrix address components ----
    const int q   = lid >> 3;   // matrix index 0..3
    const int seg = lid & 7;    // row within matrix
    const int rowA0 = wm * 32 + seg + ((q & 1) << 3);
    const int chA   = q >> 1;
    const int rowB0 = wn * 64 + seg + ((q >> 1) << 3);
    const int chB   = q & 1;

    float acc[2][8][4];
    #pragma unroll
    for (int am = 0; am < 2; ++am)
        #pragma unroll
        for (int bn = 0; bn < 8; ++bn)
            #pragma unroll
            for (int r = 0; r < 4; ++r) acc[am][bn][r] = 0.f;

    const uint32_t aBases[3] = { base + T_AHI, base + T_AHI, base + T_ALO };
    const uint32_t bBases[3] = { base + T_BHI, base + T_BLO, base + T_BHI };

    #pragma unroll
    for (int pass = 0; pass < 3; ++pass) {
        const uint32_t aB = aBases[pass];
        const uint32_t bB = bBases[pass];
        #pragma unroll
        for (int ks = 0; ks < 4; ++ks) {
            uint32_t af[2][4];
            #pragma unroll
            for (int am = 0; am < 2; ++am) {
                int row = rowA0 + am * 16;
                int ch  = (chA + 2 * ks) ^ (row & 7);
                ldsm_x4(af[am][0], af[am][1], af[am][2], af[am][3],
                        aB + row * 128 + (ch << 4));
            }
            uint32_t bf[8][2];
            #pragma unroll
            for (int bn2 = 0; bn2 < 4; ++bn2) {
                int row = rowB0 + bn2 * 16;
                int ch  = (chB + 2 * ks) ^ (row & 7);
                ldsm_x4(bf[bn2 * 2][0], bf[bn2 * 2][1],
                        bf[bn2 * 2 + 1][0], bf[bn2 * 2 + 1][1],
                        bB + row * 128 + (ch << 4));
            }
            #pragma unroll
            for (int am = 0; am < 2; ++am)
                #pragma unroll
                for (int bn = 0; bn < 8; ++bn)
                    mma_16816(acc[am][bn], af[am], bf[bn]);
        }
    }

    // ---- epilogue: k = (v+coeff)^deg; off-diag tiles count both triangles ----
    const float coeff = scal_as_float(coeff_p);
    const int   deg   = scal_as_int(degree_p);
    const float* s_wJ = (const float*)(smem + OFF_WJ);
    const float* s_yI = (const float*)(smem + OFF_YI);
    const float* s_wI = (const float*)(smem + OFF_WI);
    const float* s_yJ = (const float*)(smem + OFF_YJ);

    const int rBase = wm * 32 + (lid >> 2);
    const int cBase = wn * 64 + 2 * (lid & 3);

    float part = 0.f;
    #pragma unroll
    for (int am = 0; am < 2; ++am) {
        const int r0i = rBase + am * 16;
        const float yr0 = s_yI[r0i],     yr1 = s_yI[r0i + 8];
        const float wr0 = s_wI[r0i],     wr1 = s_wI[r0i + 8];
        float s0w = 0.f, s1w = 0.f;      // wJ-weighted col sums (rows r, r+8)
        float s0y = 0.f, s1y = 0.f;      // yJ-weighted col sums
        #pragma unroll
        for (int bn = 0; bn < 8; ++bn) {
            const int c0i = cBase + bn * 8;
            const float wc0 = s_wJ[c0i], wc1 = s_wJ[c0i + 1];
            const float yc0 = s_yJ[c0i], yc1 = s_yJ[c0i + 1];
            float k0, k1, k2, k3;
            if (deg == 3) {
                float v0 = acc[am][bn][0] + coeff;
                float v1 = acc[am][bn][1] + coeff;
                float v2 = acc[am][bn][2] + coeff;
                float v3 = acc[am][bn][3] + coeff;
                k0 = v0 * v0 * v0; k1 = v1 * v1 * v1;
                k2 = v2 * v2 * v2; k3 = v3 * v3 * v3;
            } else {
                float v[4], kk[4];
                #pragma unroll
                for (int r = 0; r < 4; ++r) {
                    v[r] = acc[am][bn][r] + coeff;
                    float p = 1.f;
                    for (int d = 0; d < deg; ++d) p *= v[r];
                    kk[r] = p;
                }
                k0 = kk[0]; k1 = kk[1]; k2 = kk[2]; k3 = kk[3];
            }
            s0w = fmaf(wc0, k0, s0w); s0w = fmaf(wc1, k1, s0w);
            s1w = fmaf(wc0, k2, s1w); s1w = fmaf(wc1, k3, s1w);
            s0y = fmaf(yc0, k0, s0y); s0y = fmaf(yc1, k1, s0y);
            s1y = fmaf(yc0, k2, s1y); s1y = fmaf(yc1, k3, s1y);
        }
        part = fmaf(yr0, s0w, part);
        part = fmaf(yr1, s1w, part);
        if (offdiag) {
            part = fmaf(wr0, s0y, part);
            part = fmaf(wr1, s1y, part);
        }
    }

    // ---- block reduce -> global double atomic ----
    #pragma unroll
    for (int o = 16; o > 0; o >>= 1)
        part += __shfl_down_sync(0xffffffffu, part, o);
    __shared__ float red[8];
    if (lid == 0) red[wid] = part;
    __syncthreads();
    if (tid == 0) {
        float s = 0.f;
        #pragma unroll
        for (int w = 0; w < 8; ++w) s += red[w];
        atomicAdd(&g_Q, (double)s);
    }
}

__global__ void svm_fin_kernel(const float* __restrict__ b,
                               const int*   __restrict__ C_p,
                               const int*   __restrict__ lambd_p,
                               float* __restrict__ out) {
    double C  = (double)scal_as_float(C_p);
    double la = (double)scal_as_float(lambd_p);
    double Q = g_Q, Sa = g_Sa, Sxi = g_Sxi, Sy = g_Sy;
    double loss = 0.5 * Sa + C * Sxi
                + la * ((Q + (double)b[0] * Sy + Sxi) / (double)NN - 1.0);
    out[0] = (float)loss;
}

// ---------------- launch ----------------
extern "C" void kernel_launch(void* const* d_in, const int* in_sizes, int n_in,
                              void* d_out, int out_size) {
    const float* x      = (const float*)d_in[0];
    const float* y      = (const float*)d_in[1];
    const float* alpha  = (const float*)d_in[2];
    const float* xi     = (const float*)d_in[3];
    const float* b      = (const float*)d_in[4];
    const int*   coeff  = (const int*)d_in[5];
    const int*   degree = (const int*)d_in[6];
    const int*   Cc     = (const int*)d_in[7];
    const int*   lambd  = (const int*)d_in[8];
    float* out = (float*)d_out;

    static bool attr_set = false;
    if (!attr_set) {
        cudaFuncSetAttribute(svm_quad_mma_kernel,
                             cudaFuncAttributeMaxDynamicSharedMemorySize, SMEM_BYTES);
        attr_set = true;
    }

    svm_zero_kernel<<<1, 1>>>();
    svm_prep_kernel<<<256, 256>>>(x, alpha, xi, y);
    svm_quad_mma_kernel<<<NPAIRS, 256, SMEM_BYTES>>>(y, coeff, degree);
    svm_fin_kernel<<<1, 1>>>(b, Cc, lambd, out);
}

// round 6
// speedup vs baseline: 6.2231x; 1.5157x over previous
#include <cuda_runtime.h>
#include <cuda_bf16.h>
#include <cstdint>

#define NN 16384
#define DD 64
#define BLK 128           // CTA tile is BLK x BLK
#define NTILES (NN / BLK) // 128
#define NPAIRS (NTILES * (NTILES + 1) / 2)   // 8256 upper-tri tiles

// ---------------- device scratch (no allocations allowed) ----------------
__device__ double g_Q;
__device__ double g_Sa, g_Sxi, g_Sy;
__device__ float  g_w[NN];
__device__ __align__(128) __nv_bfloat16 g_hi[NN * DD];
__device__ __align__(128) __nv_bfloat16 g_lo[NN * DD];

// ---------------- helpers ----------------
__device__ __forceinline__ uint32_t smem_u32(const void* p) {
    uint32_t a;
    asm("{ .reg .u64 t; cvta.to.shared.u64 t, %1; cvt.u32.u64 %0, t; }"
        : "=r"(a) : "l"(p));
    return a;
}

#define CP_ASYNC16(dst, src) \
    asm volatile("cp.async.cg.shared.global [%0], [%1], 16;" \
                 :: "r"(dst), "l"(src) : "memory")
#define CP_COMMIT() asm volatile("cp.async.commit_group;" ::: "memory")
#define CP_WAIT0()  asm volatile("cp.async.wait_group 0;" ::: "memory")

__device__ __forceinline__ void ldsm_x4(uint32_t& r0, uint32_t& r1,
                                        uint32_t& r2, uint32_t& r3, uint32_t addr) {
    asm volatile("ldmatrix.sync.aligned.m8n8.x4.shared.b16 {%0,%1,%2,%3}, [%4];"
                 : "=r"(r0), "=r"(r1), "=r"(r2), "=r"(r3) : "r"(addr));
}

__device__ __forceinline__ void mma_16816(float* c, const uint32_t* a, const uint32_t* b) {
    asm volatile(
        "mma.sync.aligned.m16n8k16.row.col.f32.bf16.bf16.f32 "
        "{%0,%1,%2,%3}, {%4,%5,%6,%7}, {%8,%9}, {%0,%1,%2,%3};"
        : "+f"(c[0]), "+f"(c[1]), "+f"(c[2]), "+f"(c[3])
        : "r"(a[0]), "r"(a[1]), "r"(a[2]), "r"(a[3]), "r"(b[0]), "r"(b[1]));
}

// scalars may be int32 or float32 bit patterns
__device__ __forceinline__ float scal_as_float(const int* p) {
    int v = *p;
    if (v < 0 || v >= 0x00800000) return __int_as_float(v);
    return (float)v;
}
__device__ __forceinline__ int scal_as_int(const int* p) {
    int v = *p;
    if (v < 0 || v >= 0x00800000) return (int)(__int_as_float(v) + 0.5f);
    return v;
}

// ---------------- small kernels ----------------
__global__ void svm_zero_kernel() {
    g_Q = 0.0; g_Sa = 0.0; g_Sxi = 0.0; g_Sy = 0.0;
}

// relu sums + w + bf16 hi/lo split of x
__global__ void svm_prep_kernel(const float* __restrict__ x,
                                const float* __restrict__ alpha,
                                const float* __restrict__ xi,
                                const float* __restrict__ y) {
    int i = blockIdx.x * blockDim.x + threadIdx.x;
    for (int e = i; e < NN * DD; e += gridDim.x * blockDim.x) {
        float v = x[e];
        __nv_bfloat16 h = __float2bfloat16_rn(v);
        g_hi[e] = h;
        g_lo[e] = __float2bfloat16_rn(v - __bfloat162float(h));
    }
    float a = 0.f, xr = 0.f, yv = 0.f;
    if (i < NN) {
        a  = fmaxf(alpha[i], 0.f);
        xr = fmaxf(xi[i], 0.f);
        yv = y[i];
        g_w[i] = a * yv;
    }
    #pragma unroll
    for (int o = 16; o > 0; o >>= 1) {
        a  += __shfl_down_sync(0xffffffffu, a,  o);
        xr += __shfl_down_sync(0xffffffffu, xr, o);
        yv += __shfl_down_sync(0xffffffffu, yv, o);
    }
    if ((threadIdx.x & 31) == 0 && i < NN) {
        atomicAdd(&g_Sa,  (double)a);
        atomicAdd(&g_Sxi, (double)xr);
        atomicAdd(&g_Sy,  (double)yv);
    }
}

// ---------------- main Gram-tile kernel (upper-tri, mma.sync bf16) ----------------
// smem tiles: 128 rows x 64 bf16 (128B/row), SW128 chunk swizzle:
//   byte off = row*128 + ((c16 ^ (row&7)) * 16)
#define T_AHI 0
#define T_ALO 16384
#define T_BHI 32768
#define T_BLO 49152
#define OFF_WJ 65536
#define OFF_YI 66048
#define OFF_WI 66560
#define OFF_YJ 67072
#define SMEM_BYTES (67584 + 256)

__global__ __launch_bounds__(256, 2)
void svm_quad_mma_kernel(const float* __restrict__ y,
                         const int* __restrict__ coeff_p,
                         const int* __restrict__ degree_p) {
    extern __shared__ char smem_raw[];
    const uint32_t raw = smem_u32(smem_raw);
    const uint32_t base = (raw + 127u) & ~127u;
    char* smem = smem_raw + (base - raw);

    const int tid = threadIdx.x;
    const int wid = tid >> 5;
    const int lid = tid & 31;
    const int wm  = wid & 3;   // 4 warps along M
    const int wn  = wid >> 2;  // 2 warps along N

    // ---- triangular decode: blockIdx.x -> (I, J), I <= J ----
    int idx = blockIdx.x;
    int I = (int)((2.0 * NTILES + 1.0
                   - sqrt((2.0 * NTILES + 1.0) * (2.0 * NTILES + 1.0) - 8.0 * idx)) * 0.5);
    if (I > NTILES - 1) I = NTILES - 1;
    if (I < 0) I = 0;
    #pragma unroll 1
    while (I > 0 && (I * NTILES - (I * (I - 1)) / 2) > idx) --I;
    #pragma unroll 1
    while (((I + 1) * NTILES - ((I + 1) * I) / 2) <= idx) ++I;
    const int J = I + (idx - (I * NTILES - (I * (I - 1)) / 2));
    const int bi = I * BLK;
    const int bj = J * BLK;
    const bool offdiag = (I != J);

    // ---- async tile loads (4 x 1024 x 16B chunks, swizzled) ----
    {
        const char* sAhi = (const char*)(g_hi + (size_t)bi * DD);
        const char* sAlo = (const char*)(g_lo + (size_t)bi * DD);
        const char* sBhi = (const char*)(g_hi + (size_t)bj * DD);
        const char* sBlo = (const char*)(g_lo + (size_t)bj * DD);
        #pragma unroll
        for (int it = 0; it < 4; ++it) {
            int i = tid + it * 256;        // 0..1023 = row*8 + c16
            int row = i >> 3, c16 = i & 7;
            int sw = row * 128 + ((c16 ^ (row & 7)) << 4);
            int lin = i * 16;
            CP_ASYNC16(base + T_AHI + sw, sAhi + lin);
            CP_ASYNC16(base + T_ALO + sw, sAlo + lin);
            CP_ASYNC16(base + T_BHI + sw, sBhi + lin);
            CP_ASYNC16(base + T_BLO + sw, sBlo + lin);
        }
        CP_COMMIT();
        // weight vectors via regular ld/st (overlap with cp.async in flight)
        if (tid < 128) {
            *(float*)(smem + OFF_WJ + tid * 4) = g_w[bj + tid];
            *(float*)(smem + OFF_YI + tid * 4) = y[bi + tid];
            *(float*)(smem + OFF_WI + tid * 4) = g_w[bi + tid];
            *(float*)(smem + OFF_YJ + tid * 4) = y[bj + tid];
        }
        CP_WAIT0();
    }
    __syncthreads();

    // ---- per-lane ldmatrix address components ----
    const int q   = lid >> 3;   // matrix index 0..3
    const int seg = lid & 7;    // row within matrix
    const int rowA0 = wm * 32 + seg + ((q & 1) << 3);
    const int chA   = q >> 1;
    const int rowB0 = wn * 64 + seg + ((q >> 1) << 3);
    const int chB   = q & 1;

    float acc[2][8][4];
    #pragma unroll
    for (int am = 0; am < 2; ++am)
        #pragma unroll
        for (int bn = 0; bn < 8; ++bn)
            #pragma unroll
            for (int r = 0; r < 4; ++r) acc[am][bn][r] = 0.f;

    const uint32_t aBases[3] = { base + T_AHI, base + T_AHI, base + T_ALO };
    const uint32_t bBases[3] = { base + T_BHI, base + T_BLO, base + T_BHI };

    #pragma unroll
    for (int pass = 0; pass < 3; ++pass) {
        const uint32_t aB = aBases[pass];
        const uint32_t bB = bBases[pass];
        #pragma unroll
        for (int ks = 0; ks < 4; ++ks) {
            uint32_t af[2][4];
            #pragma unroll
            for (int am = 0; am < 2; ++am) {
                int row = rowA0 + am * 16;
                int ch  = (chA + 2 * ks) ^ (row & 7);
                ldsm_x4(af[am][0], af[am][1], af[am][2], af[am][3],
                        aB + row * 128 + (ch << 4));
            }
            uint32_t bf[8][2];
            #pragma unroll
            for (int bn2 = 0; bn2 < 4; ++bn2) {
                int row = rowB0 + bn2 * 16;
                int ch  = (chB + 2 * ks) ^ (row & 7);
                ldsm_x4(bf[bn2 * 2][0], bf[bn2 * 2][1],
                        bf[bn2 * 2 + 1][0], bf[bn2 * 2 + 1][1],
                        bB + row * 128 + (ch << 4));
            }
            #pragma unroll
            for (int am = 0; am < 2; ++am)
                #pragma unroll
                for (int bn = 0; bn < 8; ++bn)
                    mma_16816(acc[am][bn], af[am], bf[bn]);
        }
    }

    // ---- epilogue: k = (v+coeff)^deg; off-diag tiles count both triangles ----
    const float coeff = scal_as_float(coeff_p);
    const int   deg   = scal_as_int(degree_p);
    const float* s_wJ = (const float*)(smem + OFF_WJ);
    const float* s_yI = (const float*)(smem + OFF_YI);
    const float* s_wI = (const float*)(smem + OFF_WI);
    const float* s_yJ = (const float*)(smem + OFF_YJ);

    const int rBase = wm * 32 + (lid >> 2);
    const int cBase = wn * 64 + 2 * (lid & 3);

    float part = 0.f;
    #pragma unroll
    for (int am = 0; am < 2; ++am) {
        const int r0i = rBase + am * 16;
        const float yr0 = s_yI[r0i],     yr1 = s_yI[r0i + 8];
        const float wr0 = s_wI[r0i],     wr1 = s_wI[r0i + 8];
        float s0w = 0.f, s1w = 0.f;
        float s0y = 0.f, s1y = 0.f;
        #pragma unroll
        for (int bn = 0; bn < 8; ++bn) {
            const int c0i = cBase + bn * 8;
            const float wc0 = s_wJ[c0i], wc1 = s_wJ[c0i + 1];
            const float yc0 = s_yJ[c0i], yc1 = s_yJ[c0i + 1];
            float k0, k1, k2, k3;
            if (deg == 3) {
                float v0 = acc[am][bn][0] + coeff;
                float v1 = acc[am][bn][1] + coeff;
                float v2 = acc[am][bn][2] + coeff;
                float v3 = acc[am][bn][3] + coeff;
                k0 = v0 * v0 * v0; k1 = v1 * v1 * v1;
                k2 = v2 * v2 * v2; k3 = v3 * v3 * v3;
            } else {
                float v[4], kk[4];
                #pragma unroll
                for (int r = 0; r < 4; ++r) {
                    v[r] = acc[am][bn][r] + coeff;
                    float p = 1.f;
                    for (int d = 0; d < deg; ++d) p *= v[r];
                    kk[r] = p;
                }
                k0 = kk[0]; k1 = kk[1]; k2 = kk[2]; k3 = kk[3];
            }
            s0w = fmaf(wc0, k0, s0w); s0w = fmaf(wc1, k1, s0w);
            s1w = fmaf(wc0, k2, s1w); s1w = fmaf(wc1, k3, s1w);
            s0y = fmaf(yc0, k0, s0y); s0y = fmaf(yc1, k1, s0y);
            s1y = fmaf(yc0, k2, s1y); s1y = fmaf(yc1, k3, s1y);
        }
        part = fmaf(yr0, s0w, part);
        part = fmaf(yr1, s1w, part);
        if (offdiag) {
            part = fmaf(wr0, s0y, part);
            part = fmaf(wr1, s1y, part);
        }
    }

    // ---- block reduce -> global double atomic ----
    #pragma unroll
    for (int o = 16; o > 0; o >>= 1)
        part += __shfl_down_sync(0xffffffffu, part, o);
    __shared__ float red[8];
    if (lid == 0) red[wid] = part;
    __syncthreads();
    if (tid == 0) {
        float s = 0.f;
        #pragma unroll
        for (int w = 0; w < 8; ++w) s += red[w];
        atomicAdd(&g_Q, (double)s);
    }
}

__global__ void svm_fin_kernel(const float* __restrict__ b,
                               const int*   __restrict__ C_p,
                               const int*   __restrict__ lambd_p,
                               float* __restrict__ out) {
    double C  = (double)scal_as_float(C_p);
    double la = (double)scal_as_float(lambd_p);
    double Q = g_Q, Sa = g_Sa, Sxi = g_Sxi, Sy = g_Sy;
    double loss = 0.5 * Sa + C * Sxi
                + la * ((Q + (double)b[0] * Sy + Sxi) / (double)NN - 1.0);
    out[0] = (float)loss;
}

// ---------------- launch ----------------
extern "C" void kernel_launch(void* const* d_in, const int* in_sizes, int n_in,
                              void* d_out, int out_size) {
    const float* x      = (const float*)d_in[0];
    const float* y      = (const float*)d_in[1];
    const float* alpha  = (const float*)d_in[2];
    const float* xi     = (const float*)d_in[3];
    const float* b      = (const float*)d_in[4];
    const int*   coeff  = (const int*)d_in[5];
    const int*   degree = (const int*)d_in[6];
    const int*   Cc     = (const int*)d_in[7];
    const int*   lambd  = (const int*)d_in[8];
    float* out = (float*)d_out;

    static bool attr_set = false;
    if (!attr_set) {
        cudaFuncSetAttribute(svm_quad_mma_kernel,
                             cudaFuncAttributeMaxDynamicSharedMemorySize, SMEM_BYTES);
        attr_set = true;
    }

    svm_zero_kernel<<<1, 1>>>();
    svm_prep_kernel<<<256, 256>>>(x, alpha, xi, y);
    svm_quad_mma_kernel<<<NPAIRS, 256, SMEM_BYTES>>>(y, coeff, degree);
    svm_fin_kernel<<<1, 1>>>(b, Cc, lambd, out);
}